// round 11
// baseline (speedup 1.0000x reference)
#include <cuda_runtime.h>
#include <cstdint>

#define NN 50000
#define NE 800000
#define C  96
#define TM 128
#define NTILES 391            // ceil(NN/TM)
#define NPAIRS 196            // ceil(NTILES/2)
#define NB 148                // persistent blocks (co-resident, 1/SM)
#define NT 1024
#define GSZ (NB * NT)
#define CHUNK 338             // ceil(NN/NB)

// ---------------- scratch (device globals; no allocation allowed) ----------
__device__ float g_H[NN * C];
__device__ float g_P[NN * C];
__device__ int   g_cnt[NN];
__device__ int   g_cursor[NN];
__device__ int   g_rowptr[NN + 1];
__device__ int2  g_edge[NE];          // (src, bits(w)) grouped by dst
__device__ int   g_bsum[NB];
__device__ unsigned g_bar_count;
__device__ unsigned g_bar_gen;

// ---------------- software grid barrier (all NB blocks co-resident) --------
__device__ __forceinline__ void grid_barrier() {
    __syncthreads();
    if (threadIdx.x == 0) {
        unsigned gen = *(volatile unsigned*)&g_bar_gen;
        __threadfence();
        if (atomicAdd(&g_bar_count, 1u) == NB - 1) {
            g_bar_count = 0u;
            __threadfence();
            *(volatile unsigned*)&g_bar_gen = gen + 1u;
        } else {
            while (*(volatile unsigned*)&g_bar_gen == gen) __nanosleep(64);
        }
    }
    __syncthreads();
}

// ---------------- GEMM tile (512 threads per tile, packed f32x2 math) ------
// ltid in [0,512): cg = ltid&7 (12 ch = 6 f32x2 pairs), ng = ltid>>3 (2 nodes).
// Only X is register-prefetched; W relies on 32-warp latency hiding.
__device__ __forceinline__ void gemm_tile(const float* __restrict__ in,
                                          const float* __restrict__ W,
                                          float* __restrict__ out,
                                          int cin, int tile,
                                          float (*Xs)[33], float (*Ws)[96]) {
    const int tid = threadIdx.x;        // 0..1023
    const int ltid = tid & 511;
    const int cg = ltid & 7;
    const int ng = ltid >> 3;           // 0..63 -> nodes ng*2, ng*2+1
    const int node0 = tile * TM;

    // X-load geometry (per tile, 2 float4 per thread per chunk)
    int xr[2], xkq[2];
    const float* xbase[2];
#pragma unroll
    for (int i = 0; i < 2; i++) {
        int li = ltid + i * 512;
        xr[i] = li >> 3; xkq[i] = li & 7;
        int nd = node0 + xr[i];
        xbase[i] = (nd < NN) ? in + (size_t)nd * cin : nullptr;
    }

    // 2 nodes x 6 channel-pairs, packed f32x2 accumulators
    unsigned long long acc2[2][6];
#pragma unroll
    for (int i = 0; i < 2; i++)
#pragma unroll
        for (int j = 0; j < 6; j++) acc2[i][j] = 0ull;

    const int nkc = cin >> 5;

    // prologue: prefetch X chunk 0
    float4 px[2];
#pragma unroll
    for (int i = 0; i < 2; i++)
        px[i] = xbase[i] ? __ldcg((const float4*)(xbase[i]) + xkq[i])
                         : make_float4(0.f, 0.f, 0.f, 0.f);

    for (int kc = 0; kc < nkc; kc++) {
        // W chunk (32x96 = 768 float4) loaded by half 0 (512 thr, <=2 each)
        if (tid < 512) {
#pragma unroll
            for (int i = 0; i < 2; i++) {
                int li = tid + i * 512;
                if (li < 768) {
                    int r = li / 24, cq = li % 24;
                    float4 v = ((const float4*)(W + (size_t)(kc * 32 + r) * 96))[cq];
                    *(float4*)&Ws[r][cq * 4] = v;
                }
            }
        }
        // commit prefetched X chunk kc
#pragma unroll
        for (int i = 0; i < 2; i++) {
            Xs[xr[i]][xkq[i] * 4 + 0] = px[i].x;
            Xs[xr[i]][xkq[i] * 4 + 1] = px[i].y;
            Xs[xr[i]][xkq[i] * 4 + 2] = px[i].z;
            Xs[xr[i]][xkq[i] * 4 + 3] = px[i].w;
        }
        __syncthreads();

        // prefetch X chunk kc+1 (overlaps with compute)
        if (kc + 1 < nkc) {
            const int koff = (kc + 1) * 32;
#pragma unroll
            for (int i = 0; i < 2; i++)
                px[i] = xbase[i] ? __ldcg((const float4*)(xbase[i] + koff) + xkq[i])
                                 : make_float4(0.f, 0.f, 0.f, 0.f);
        }

#pragma unroll
        for (int k = 0; k < 32; k++) {
            const unsigned long long* wp =
                (const unsigned long long*)&Ws[k][cg * 12];
            unsigned long long w[6];
#pragma unroll
            for (int j = 0; j < 6; j++) w[j] = wp[j];
#pragma unroll
            for (int i = 0; i < 2; i++) {
                unsigned xb = __float_as_uint(Xs[ng * 2 + i][k]);
                unsigned long long xx;
                asm("mov.b64 %0, {%1, %1};" : "=l"(xx) : "r"(xb));
#pragma unroll
                for (int j = 0; j < 6; j++)
                    asm("fma.rn.f32x2 %0, %1, %2, %0;"
                        : "+l"(acc2[i][j]) : "l"(xx), "l"(w[j]));
            }
        }
        __syncthreads();
    }

#pragma unroll
    for (int i = 0; i < 2; i++) {
        int nd = node0 + ng * 2 + i;
        if (nd < NN) {
            unsigned long long* o =
                (unsigned long long*)(out + (size_t)nd * 96 + cg * 12);
#pragma unroll
            for (int j = 0; j < 6; j++) o[j] = acc2[i][j];
        }
    }
}

// ---------------- gather phase: warp per node, E[8] + 2x v[4] batches -------
__device__ __forceinline__ void gather_phase(const float* __restrict__ h,
                                             const float* __restrict__ b,
                                             float* __restrict__ out, int relu) {
    const int lane = threadIdx.x & 31;
    const int warp = threadIdx.x >> 5;
    const int gw = blockIdx.x * 32 + warp;    // 4736 warps total
    const float4* __restrict__ h4 = (const float4*)h;

    for (int node = gw; node < NN; node += NB * 32) {
        if (lane < 24) {
            const int beg = __ldcg(&g_rowptr[node]);
            const int end = __ldcg(&g_rowptr[node + 1]);

            float4 acc = make_float4(0.f, 0.f, 0.f, 0.f);
            int e = beg;
            for (; e + 8 <= end; e += 8) {
                int2 E[8];
#pragma unroll
                for (int j = 0; j < 8; j++) E[j] = __ldcg(&g_edge[e + j]);
#pragma unroll
                for (int half = 0; half < 2; half++) {
                    float4 v[4];
#pragma unroll
                    for (int j = 0; j < 4; j++)
                        v[j] = __ldcg(h4 + (size_t)E[half * 4 + j].x * 24 + lane);
#pragma unroll
                    for (int j = 0; j < 4; j++) {
                        float w = __int_as_float(E[half * 4 + j].y);
                        acc.x += v[j].x * w; acc.y += v[j].y * w;
                        acc.z += v[j].z * w; acc.w += v[j].w * w;
                    }
                }
            }
            for (; e + 4 <= end; e += 4) {
                int2 E[4];
#pragma unroll
                for (int j = 0; j < 4; j++) E[j] = __ldcg(&g_edge[e + j]);
                float4 v[4];
#pragma unroll
                for (int j = 0; j < 4; j++) v[j] = __ldcg(h4 + (size_t)E[j].x * 24 + lane);
#pragma unroll
                for (int j = 0; j < 4; j++) {
                    float w = __int_as_float(E[j].y);
                    acc.x += v[j].x * w; acc.y += v[j].y * w;
                    acc.z += v[j].z * w; acc.w += v[j].w * w;
                }
            }
            for (; e < end; e++) {
                int2 E = __ldcg(&g_edge[e]);
                float4 v = __ldcg(h4 + (size_t)E.x * 24 + lane);
                float w = __int_as_float(E.y);
                acc.x += v.x * w; acc.y += v.y * w; acc.z += v.z * w; acc.w += v.w * w;
            }

            const float dii = 1.0f / (float)(__ldcg(&g_cnt[node]) + 1);  // dis^2 exact
            float4 hv = __ldcg(h4 + (size_t)node * 24 + lane);
            float4 bv = ((const float4*)b)[lane];
            acc.x += hv.x * dii + bv.x;
            acc.y += hv.y * dii + bv.y;
            acc.z += hv.z * dii + bv.z;
            acc.w += hv.w * dii + bv.w;
            if (relu) {
                acc.x = fmaxf(acc.x, 0.f); acc.y = fmaxf(acc.y, 0.f);
                acc.z = fmaxf(acc.z, 0.f); acc.w = fmaxf(acc.w, 0.f);
            }
            ((float4*)out)[(size_t)node * 24 + lane] = acc;
        }
    }
}

// ---------------- the one persistent kernel --------------------------------
__global__ __launch_bounds__(NT, 1) void gcn_mega_kernel(
    const float* __restrict__ x, const int* __restrict__ ei,
    const float* __restrict__ W1, const float* __restrict__ b1,
    const float* __restrict__ W2, const float* __restrict__ b2,
    const float* __restrict__ W3, const float* __restrict__ b3,
    const float* __restrict__ W4, const float* __restrict__ b4,
    float* __restrict__ out)
{
    __shared__ float Xs[2][TM][33];     // per-tile X buffers
    __shared__ float Ws[32][96];        // shared W chunk
    int* sc = (int*)Ws;                 // scan scratch (NT ints fits 12KB? 1024*4=4KB OK)

    const int tid = threadIdx.x;
    const int gtid = blockIdx.x * NT + tid;

    // P0: zero cnt + cursor
    for (int i = gtid; i < NN; i += GSZ) { g_cnt[i] = 0; g_cursor[i] = 0; }
    grid_barrier();

    // P1: degree count
    for (int e = gtid; e < NE; e += GSZ) atomicAdd(&g_cnt[ei[NE + e]], 1);
    grid_barrier();

    // P2a: per-thread element + block exclusive scan (CHUNK=338 <= NT)
    const int base = blockIdx.x * CHUNK;
    const int lim = min(base + CHUNK, NN);
    const int myi = base + tid;
    int mysum = (myi < lim) ? __ldcg(&g_cnt[myi]) : 0;
    sc[tid] = mysum;
    __syncthreads();
    for (int off = 1; off < NT; off <<= 1) {
        int v = (tid >= off) ? sc[tid - off] : 0;
        __syncthreads();
        sc[tid] += v;
        __syncthreads();
    }
    int myexcl = sc[tid] - mysum;
    if (tid == NT - 1) g_bsum[blockIdx.x] = sc[tid];
    grid_barrier();

    // P2b: warp-parallel exclusive scan of NB block sums (block 0, warp 0)
    if (blockIdx.x == 0 && tid < 32) {
        int carry = 0;
        for (int b0 = 0; b0 < NB; b0 += 32) {
            int i = b0 + tid;
            int v = (i < NB) ? __ldcg(&g_bsum[i]) : 0;
            int orig = v;
#pragma unroll
            for (int o = 1; o < 32; o <<= 1) {
                int t = __shfl_up_sync(0xffffffffu, v, o);
                if ((tid & 31) >= o) v += t;
            }
            if (i < NB) g_bsum[i] = carry + v - orig;   // exclusive
            carry += __shfl_sync(0xffffffffu, v, 31);
        }
        if (tid == 0) g_rowptr[NN] = carry;
    }
    grid_barrier();

    // P2c: final rowptr
    if (myi < lim) g_rowptr[myi] = __ldcg(&g_bsum[blockIdx.x]) + myexcl;
    grid_barrier();

    // P3: fill CSR with precomputed edge weight
    for (int e = gtid; e < NE; e += GSZ) {
        int s = ei[e];
        int d = ei[NE + e];
        float w = rsqrtf((float)((__ldcg(&g_cnt[s]) + 1) * (__ldcg(&g_cnt[d]) + 1)));
        int pos = atomicAdd(&g_cursor[d], 1);
        g_edge[__ldcg(&g_rowptr[d]) + pos] = make_int2(s, __float_as_int(w));
    }
    grid_barrier();

    // layers
    const float* gin[4] = { x, g_P, g_P, g_P };
    const float* gW[4]  = { W1, W2, W3, W4 };
    const float* gb[4]  = { b1, b2, b3, b4 };
    float*       gout[4] = { g_P, g_P, g_P, out };
    const int    gcin[4] = { 128, 96, 96, 96 };

    const int half = tid >> 9;          // 0 or 1
    for (int l = 0; l < 4; l++) {
        for (int p = blockIdx.x; p < NPAIRS; p += NB) {
            int tile = 2 * p + half;
            if (tile >= NTILES) tile = NTILES - 1;   // tail: duplicate write, benign
            gemm_tile(gin[l], gW[l], g_H, gcin[l], tile, Xs[half], Ws);
        }
        grid_barrier();
        gather_phase(g_H, gb[l], gout[l], (l < 3) ? 1 : 0);
        if (l < 3) grid_barrier();
    }
}

// ---------------- launch ----------------------------------------------------
extern "C" void kernel_launch(void* const* d_in, const int* in_sizes, int n_in,
                              void* d_out, int out_size) {
    const float* x  = (const float*)d_in[0];
    const int*   ei = (const int*)d_in[1];   // int32 (JAX demotes int64)
    const float* W1 = (const float*)d_in[2];
    const float* b1 = (const float*)d_in[3];
    const float* W2 = (const float*)d_in[4];
    const float* b2 = (const float*)d_in[5];
    const float* W3 = (const float*)d_in[6];
    const float* b3 = (const float*)d_in[7];
    const float* W4 = (const float*)d_in[8];
    const float* b4 = (const float*)d_in[9];
    float* out = (float*)d_out;

    gcn_mega_kernel<<<NB, NT>>>(x, ei, W1, b1, W2, b2, W3, b3, W4, b4, out);
}

// round 12
// speedup vs baseline: 1.0885x; 1.0885x over previous
#include <cuda_runtime.h>
#include <cstdint>

#define NN 50000
#define NE 800000
#define C  96
#define TM 128
#define NTILES 391            // ceil(NN/TM)
#define NPAIRS 196            // ceil(NTILES/2)
#define NB 148                // persistent blocks (co-resident, 1/SM)
#define NB_CSR 48             // blocks doing CSR build during layer-1 GEMM
#define NG1 (NB - NB_CSR)     // blocks doing layer-1 GEMM
#define NT 512
#define GSZC (NB_CSR * NT)
#define CHUNKC 1042           // ceil(NN/NB_CSR)

// ---------------- scratch (device globals; no allocation allowed) ----------
__device__ float g_H[NN * C];
__device__ float g_P[NN * C];
__device__ int   g_cnt[NN];
__device__ int   g_cursor[NN];
__device__ int   g_rowptr[NN + 1];
__device__ int2  g_edge[NE];          // (src, bits(w)) grouped by dst
__device__ int   g_bsum[NB];
__device__ unsigned g_bar_count, g_bar_gen;     // full-grid barrier
__device__ unsigned g_sbar_count, g_sbar_gen;   // CSR-subgroup barrier

// ---------------- barriers ---------------------------------------------------
__device__ __forceinline__ void grid_barrier() {
    __syncthreads();
    if (threadIdx.x == 0) {
        unsigned gen = *(volatile unsigned*)&g_bar_gen;
        __threadfence();
        if (atomicAdd(&g_bar_count, 1u) == NB - 1) {
            g_bar_count = 0u;
            __threadfence();
            *(volatile unsigned*)&g_bar_gen = gen + 1u;
        } else {
            while (*(volatile unsigned*)&g_bar_gen == gen) __nanosleep(64);
        }
    }
    __syncthreads();
}

__device__ __forceinline__ void sub_barrier() {   // CSR subgroup only
    __syncthreads();
    if (threadIdx.x == 0) {
        unsigned gen = *(volatile unsigned*)&g_sbar_gen;
        __threadfence();
        if (atomicAdd(&g_sbar_count, 1u) == NB_CSR - 1) {
            g_sbar_count = 0u;
            __threadfence();
            *(volatile unsigned*)&g_sbar_gen = gen + 1u;
        } else {
            while (*(volatile unsigned*)&g_sbar_gen == gen) __nanosleep(64);
        }
    }
    __syncthreads();
}

// ---------------- GEMM tile (256 threads per tile, packed f32x2 math) ------
// ltid: ng = ltid>>3 (4 nodes), cg = ltid&7 (12 channels = 6 f32x2 pairs).
// Register-prefetched W/X chunks. Ws shared between halves; Xs per-half.
__device__ __forceinline__ void gemm_tile(const float* __restrict__ in,
                                          const float* __restrict__ W,
                                          float* __restrict__ out,
                                          int cin, int tile,
                                          float (*Xs)[33], float (*Ws)[96]) {
    const int tid = threadIdx.x;        // 0..511
    const int ltid = tid & 255;
    const int cg = ltid & 7;
    const int ng = ltid >> 3;
    const int node0 = tile * TM;

    int xr[4], xkq[4];
    const float* xbase[4];
#pragma unroll
    for (int i = 0; i < 4; i++) {
        int li = ltid + i * 256;
        xr[i] = li >> 3; xkq[i] = li & 7;
        int nd = node0 + xr[i];
        xbase[i] = (nd < NN) ? in + (size_t)nd * cin : nullptr;
    }
    int wr[3], wcq[3];
#pragma unroll
    for (int i = 0; i < 3; i++) {
        int li = tid + i * 256;
        wr[i] = li / 24; wcq[i] = li % 24;
    }

    unsigned long long acc2[4][6];
#pragma unroll
    for (int i = 0; i < 4; i++)
#pragma unroll
        for (int j = 0; j < 6; j++) acc2[i][j] = 0ull;

    const int nkc = cin >> 5;

    float4 px[4], pw[3];
#pragma unroll
    for (int i = 0; i < 4; i++)
        px[i] = xbase[i] ? __ldcg((const float4*)(xbase[i]) + xkq[i])
                         : make_float4(0.f, 0.f, 0.f, 0.f);
    if (tid < 256) {
#pragma unroll
        for (int i = 0; i < 3; i++)
            pw[i] = ((const float4*)(W + (size_t)wr[i] * 96))[wcq[i]];
    }

    for (int kc = 0; kc < nkc; kc++) {
        if (tid < 256) {
#pragma unroll
            for (int i = 0; i < 3; i++)
                *(float4*)&Ws[wr[i]][wcq[i] * 4] = pw[i];
        }
#pragma unroll
        for (int i = 0; i < 4; i++) {
            Xs[xr[i]][xkq[i] * 4 + 0] = px[i].x;
            Xs[xr[i]][xkq[i] * 4 + 1] = px[i].y;
            Xs[xr[i]][xkq[i] * 4 + 2] = px[i].z;
            Xs[xr[i]][xkq[i] * 4 + 3] = px[i].w;
        }
        __syncthreads();

        if (kc + 1 < nkc) {
            const int koff = (kc + 1) * 32;
#pragma unroll
            for (int i = 0; i < 4; i++)
                px[i] = xbase[i] ? __ldcg((const float4*)(xbase[i] + koff) + xkq[i])
                                 : make_float4(0.f, 0.f, 0.f, 0.f);
            if (tid < 256) {
#pragma unroll
                for (int i = 0; i < 3; i++)
                    pw[i] = ((const float4*)(W + (size_t)(koff + wr[i]) * 96))[wcq[i]];
            }
        }

#pragma unroll
        for (int k = 0; k < 32; k++) {
            const unsigned long long* wp =
                (const unsigned long long*)&Ws[k][cg * 12];
            unsigned long long w[6];
#pragma unroll
            for (int j = 0; j < 6; j++) w[j] = wp[j];
#pragma unroll
            for (int i = 0; i < 4; i++) {
                unsigned xb = __float_as_uint(Xs[ng * 4 + i][k]);
                unsigned long long xx;
                asm("mov.b64 %0, {%1, %1};" : "=l"(xx) : "r"(xb));
#pragma unroll
                for (int j = 0; j < 6; j++)
                    asm("fma.rn.f32x2 %0, %1, %2, %0;"
                        : "+l"(acc2[i][j]) : "l"(xx), "l"(w[j]));
            }
        }
        __syncthreads();
    }

#pragma unroll
    for (int i = 0; i < 4; i++) {
        int nd = node0 + ng * 4 + i;
        if (nd < NN) {
            unsigned long long* o =
                (unsigned long long*)(out + (size_t)nd * 96 + cg * 12);
#pragma unroll
            for (int j = 0; j < 6; j++) o[j] = acc2[i][j];
        }
    }
}

// ---------------- gather phase: warp per node, int4 edge loads --------------
__device__ __forceinline__ void gather_phase(const float* __restrict__ h,
                                             const float* __restrict__ b,
                                             float* __restrict__ out, int relu) {
    const int lane = threadIdx.x & 31;
    const int warp = threadIdx.x >> 5;
    const int gw = blockIdx.x * 16 + warp;    // 2368 warps total
    const float4* __restrict__ h4 = (const float4*)h;
    const int4* __restrict__ e4 = (const int4*)g_edge;   // 2 edges per int4

    for (int node = gw; node < NN; node += NB * 16) {
        if (lane < 24) {
            const int beg = __ldcg(&g_rowptr[node]);
            const int end = __ldcg(&g_rowptr[node + 1]);

            float4 acc = make_float4(0.f, 0.f, 0.f, 0.f);
            float4 acc2 = make_float4(0.f, 0.f, 0.f, 0.f);
            int e = beg;
            // head: align e to even
            if ((e & 1) && e < end) {
                int2 E = __ldcg(&g_edge[e]);
                float4 v = __ldcg(h4 + (size_t)E.x * 24 + lane);
                float w = __int_as_float(E.y);
                acc.x += v.x * w; acc.y += v.y * w; acc.z += v.z * w; acc.w += v.w * w;
                e++;
            }
            for (; e + 8 <= end; e += 8) {
                int4 q[4];
#pragma unroll
                for (int j = 0; j < 4; j++) q[j] = __ldcg(e4 + (e >> 1) + j);
                float4 v[8];
#pragma unroll
                for (int j = 0; j < 4; j++) {
                    v[2 * j]     = __ldcg(h4 + (size_t)q[j].x * 24 + lane);
                    v[2 * j + 1] = __ldcg(h4 + (size_t)q[j].z * 24 + lane);
                }
#pragma unroll
                for (int j = 0; j < 4; j++) {
                    float w0 = __int_as_float(q[j].y);
                    float w1 = __int_as_float(q[j].w);
                    acc.x += v[2 * j].x * w0;  acc.y += v[2 * j].y * w0;
                    acc.z += v[2 * j].z * w0;  acc.w += v[2 * j].w * w0;
                    acc2.x += v[2 * j + 1].x * w1; acc2.y += v[2 * j + 1].y * w1;
                    acc2.z += v[2 * j + 1].z * w1; acc2.w += v[2 * j + 1].w * w1;
                }
            }
            for (; e + 2 <= end; e += 2) {
                int4 q = __ldcg(e4 + (e >> 1));
                float4 v0 = __ldcg(h4 + (size_t)q.x * 24 + lane);
                float4 v1 = __ldcg(h4 + (size_t)q.z * 24 + lane);
                float w0 = __int_as_float(q.y), w1 = __int_as_float(q.w);
                acc.x += v0.x * w0; acc.y += v0.y * w0;
                acc.z += v0.z * w0; acc.w += v0.w * w0;
                acc2.x += v1.x * w1; acc2.y += v1.y * w1;
                acc2.z += v1.z * w1; acc2.w += v1.w * w1;
            }
            if (e < end) {
                int2 E = __ldcg(&g_edge[e]);
                float4 v = __ldcg(h4 + (size_t)E.x * 24 + lane);
                float w = __int_as_float(E.y);
                acc.x += v.x * w; acc.y += v.y * w; acc.z += v.z * w; acc.w += v.w * w;
            }
            acc.x += acc2.x; acc.y += acc2.y; acc.z += acc2.z; acc.w += acc2.w;

            const float dii = 1.0f / (float)(__ldcg(&g_cnt[node]) + 1);  // dis^2 exact
            float4 hv = __ldcg(h4 + (size_t)node * 24 + lane);
            float4 bv = ((const float4*)b)[lane];
            acc.x += hv.x * dii + bv.x;
            acc.y += hv.y * dii + bv.y;
            acc.z += hv.z * dii + bv.z;
            acc.w += hv.w * dii + bv.w;
            if (relu) {
                acc.x = fmaxf(acc.x, 0.f); acc.y = fmaxf(acc.y, 0.f);
                acc.z = fmaxf(acc.z, 0.f); acc.w = fmaxf(acc.w, 0.f);
            }
            ((float4*)out)[(size_t)node * 24 + lane] = acc;
        }
    }
}

// ---------------- the one persistent kernel --------------------------------
__global__ __launch_bounds__(NT, 1) void gcn_mega_kernel(
    const float* __restrict__ x, const int* __restrict__ ei,
    const float* __restrict__ W1, const float* __restrict__ b1,
    const float* __restrict__ W2, const float* __restrict__ b2,
    const float* __restrict__ W3, const float* __restrict__ b3,
    const float* __restrict__ W4, const float* __restrict__ b4,
    float* __restrict__ out)
{
    __shared__ float Xs[2][TM][33];
    __shared__ float Ws[32][96];
    int* sc = (int*)Ws;                 // scan scratch (NT ints)

    const int tid = threadIdx.x;
    const int half = tid >> 8;          // 0 or 1

    if (blockIdx.x < NB_CSR) {
        // ---------------- CSR subgroup: build CSR while others do gemm L1 ---
        const int gtid = blockIdx.x * NT + tid;

        // P0: zero cnt + cursor
        for (int i = gtid; i < NN; i += GSZC) { g_cnt[i] = 0; g_cursor[i] = 0; }
        sub_barrier();

        // P1: degree count
        for (int e = gtid; e < NE; e += GSZC) atomicAdd(&g_cnt[ei[NE + e]], 1);
        sub_barrier();

        // P2a: per-thread 3 contiguous elems + block scan
        const int base = blockIdx.x * CHUNKC;
        const int lim = min(base + CHUNKC, NN);
        const int s0 = base + tid * 3;
        const int s1 = min(s0 + 3, lim);
        int mysum = 0;
        for (int i = s0; i < s1; i++) mysum += __ldcg(&g_cnt[i]);
        sc[tid] = mysum;
        __syncthreads();
        for (int off = 1; off < NT; off <<= 1) {
            int v = (tid >= off) ? sc[tid - off] : 0;
            __syncthreads();
            sc[tid] += v;
            __syncthreads();
        }
        int myexcl = sc[tid] - mysum;
        if (tid == NT - 1) g_bsum[blockIdx.x] = sc[tid];
        sub_barrier();

        // P2b: warp scan of NB_CSR block sums
        if (blockIdx.x == 0 && tid < 32) {
            int carry = 0;
            for (int b0 = 0; b0 < NB_CSR; b0 += 32) {
                int i = b0 + tid;
                int v = (i < NB_CSR) ? __ldcg(&g_bsum[i]) : 0;
                int orig = v;
#pragma unroll
                for (int o = 1; o < 32; o <<= 1) {
                    int t = __shfl_up_sync(0xffffffffu, v, o);
                    if ((tid & 31) >= o) v += t;
                }
                if (i < NB_CSR) g_bsum[i] = carry + v - orig;
                carry += __shfl_sync(0xffffffffu, v, 31);
            }
            if (tid == 0) g_rowptr[NN] = carry;
        }
        sub_barrier();

        // P2c: final rowptr
        {
            int run = __ldcg(&g_bsum[blockIdx.x]) + myexcl;
            for (int i = s0; i < s1; i++) {
                g_rowptr[i] = run;
                run += __ldcg(&g_cnt[i]);
            }
        }
        sub_barrier();

        // P3: fill CSR with precomputed edge weight
        for (int e = gtid; e < NE; e += GSZC) {
            int s = ei[e];
            int d = ei[NE + e];
            float w = rsqrtf((float)((__ldcg(&g_cnt[s]) + 1) * (__ldcg(&g_cnt[d]) + 1)));
            int pos = atomicAdd(&g_cursor[d], 1);
            g_edge[__ldcg(&g_rowptr[d]) + pos] = make_int2(s, __float_as_int(w));
        }
    } else {
        // ---------------- GEMM layer 1 (independent of CSR) ------------------
        const int g = blockIdx.x - NB_CSR;
        for (int p = g; p < NPAIRS; p += NG1) {
            int tile = 2 * p + half;
            if (tile >= NTILES) tile = NTILES - 1;
            gemm_tile(x, W1, g_H, 128, tile, Xs[half], Ws);
        }
    }
    grid_barrier();   // join: CSR done + g_H(layer1) done

    // layer 1 aggregation
    gather_phase(g_H, b1, g_P, 1);
    grid_barrier();

    // layers 2..4
    const float* gW[3]  = { W2, W3, W4 };
    const float* gb[3]  = { b2, b3, b4 };
    for (int l = 0; l < 3; l++) {
        for (int p = blockIdx.x; p < NPAIRS; p += NB) {
            int tile = 2 * p + half;
            if (tile >= NTILES) tile = NTILES - 1;
            gemm_tile(g_P, gW[l], g_H, 96, tile, Xs[half], Ws);
        }
        grid_barrier();
        gather_phase(g_H, gb[l], (l < 2) ? g_P : out, (l < 2) ? 1 : 0);
        if (l < 2) grid_barrier();
    }
}

// ---------------- launch ----------------------------------------------------
extern "C" void kernel_launch(void* const* d_in, const int* in_sizes, int n_in,
                              void* d_out, int out_size) {
    const float* x  = (const float*)d_in[0];
    const int*   ei = (const int*)d_in[1];   // int32 (JAX demotes int64)
    const float* W1 = (const float*)d_in[2];
    const float* b1 = (const float*)d_in[3];
    const float* W2 = (const float*)d_in[4];
    const float* b2 = (const float*)d_in[5];
    const float* W3 = (const float*)d_in[6];
    const float* b3 = (const float*)d_in[7];
    const float* W4 = (const float*)d_in[8];
    const float* b4 = (const float*)d_in[9];
    float* out = (float*)d_out;

    gcn_mega_kernel<<<NB, NT>>>(x, ei, W1, b1, W2, b2, W3, b3, W4, b4, out);
}